// round 2
// baseline (speedup 1.0000x reference)
#include <cuda_runtime.h>
#include <math_constants.h>

#define NHEADS 16
#define DH     64
#define ODIM   1024
#define NB     2
#define NLQ    2048
#define NLK    2048
#define BIGF   1e10f

// Scratch for projected Q/K/V (allowed: __device__ globals, no runtime alloc)
__device__ float g_QW[NB * NLQ * ODIM];
__device__ float g_KW[NB * NLK * ODIM];
__device__ float g_VW[NB * NLK * ODIM];

// ---------------------------------------------------------------------------
// Projection GEMM: C[M,N] = X[M,K] @ W[N,K]^T   (M=4096, N=K=1024)
// 64x64 tile, BK=16, 256 threads, 4x4 microtile per thread.
// ---------------------------------------------------------------------------
__global__ __launch_bounds__(256) void proj_gemm_kernel(
    const float* __restrict__ X, const float* __restrict__ W,
    float* __restrict__ C)
{
    constexpr int K = ODIM;
    constexpr int N = ODIM;
    __shared__ float As[16][64];   // [k][m]
    __shared__ float Bs[16][64];   // [k][n]

    const int tid = threadIdx.x;
    const int ty  = tid >> 4;      // 0..15 -> 4 rows
    const int tx  = tid & 15;      // 0..15 -> 4 cols
    const int m0  = blockIdx.y * 64;
    const int n0  = blockIdx.x * 64;

    const int lr = tid >> 2;          // 0..63 tile row
    const int lc = (tid & 3) * 4;     // 0,4,8,12 within BK
    const float* Xp = X + (size_t)(m0 + lr) * K + lc;
    const float* Wp = W + (size_t)(n0 + lr) * K + lc;

    float acc[4][4] = {};

    for (int k0 = 0; k0 < K; k0 += 16) {
        float4 a4 = *(const float4*)(Xp + k0);
        float4 b4 = *(const float4*)(Wp + k0);
        As[lc + 0][lr] = a4.x; As[lc + 1][lr] = a4.y;
        As[lc + 2][lr] = a4.z; As[lc + 3][lr] = a4.w;
        Bs[lc + 0][lr] = b4.x; Bs[lc + 1][lr] = b4.y;
        Bs[lc + 2][lr] = b4.z; Bs[lc + 3][lr] = b4.w;
        __syncthreads();

        #pragma unroll
        for (int kk = 0; kk < 16; kk++) {
            float4 av = *(const float4*)&As[kk][ty * 4];
            float4 bv = *(const float4*)&Bs[kk][tx * 4];
            float a[4] = {av.x, av.y, av.z, av.w};
            float b[4] = {bv.x, bv.y, bv.z, bv.w};
            #pragma unroll
            for (int i = 0; i < 4; i++)
                #pragma unroll
                for (int j = 0; j < 4; j++)
                    acc[i][j] = fmaf(a[i], b[j], acc[i][j]);
        }
        __syncthreads();
    }

    #pragma unroll
    for (int i = 0; i < 4; i++) {
        float4 o = make_float4(acc[i][0], acc[i][1], acc[i][2], acc[i][3]);
        *(float4*)&C[(size_t)(m0 + ty * 4 + i) * N + n0 + tx * 4] = o;
    }
}

// ---------------------------------------------------------------------------
// Flash-style attention over projected tensors.
// One CTA = 64 q-rows of one (batch, head). Loops over all 32 k-tiles of 64
// (NO tile skipping: the "tril incl. diagonal" penalty means degenerate rows
// average over keys tied at exactly -1e10; fp32 arithmetic here reproduces the
// reference's tie semantics so processing all tiles is exact).
// smem: Qs [d][q], KPs = Ks [d][k] reused as Ps [k][q], Vs [k][d] = 48 KB.
// ---------------------------------------------------------------------------
__global__ __launch_bounds__(256) void attn_kernel(
    const float* __restrict__ v_mask, const float* __restrict__ q_mask,
    float* __restrict__ out)
{
    __shared__ float Qs[64 * 64];   // [d][q]
    __shared__ float KPs[64 * 64];  // Ks as [d][k], then Ps as [k][q]
    __shared__ float Vs[64 * 64];   // [k][d]

    const int tid = threadIdx.x;
    const int ty  = tid >> 4;       // 0..15  -> q rows ty*4..+3
    const int tx  = tid & 15;       // 0..15  -> cols tx*4..+3
    const int q0  = blockIdx.x * 64;
    const int h   = blockIdx.y;
    const int b   = blockIdx.z;

    const float* QW = g_QW + (size_t)b * NLQ * ODIM + h * DH;
    const float* KW = g_KW + (size_t)b * NLK * ODIM + h * DH;
    const float* VW = g_VW + (size_t)b * NLK * ODIM + h * DH;
    const float* vm = v_mask + (size_t)b * NLK;

    const int lr = tid >> 2;          // 0..63 tile row for loads
    const int cb = (tid & 3) * 16;    // column base (4 float4s per thread)

    // Load Q tile transposed: Qs[d][q]
    #pragma unroll
    for (int u = 0; u < 4; u++) {
        int c = cb + u * 4;
        float4 v4 = *(const float4*)&QW[(size_t)(q0 + lr) * ODIM + c];
        Qs[(c + 0) * 64 + lr] = v4.x;
        Qs[(c + 1) * 64 + lr] = v4.y;
        Qs[(c + 2) * 64 + lr] = v4.z;
        Qs[(c + 3) * 64 + lr] = v4.w;
    }

    float o[4][4] = {};
    float mrow[4] = {-CUDART_INF_F, -CUDART_INF_F, -CUDART_INF_F, -CUDART_INF_F};
    float lrow[4] = {};

    for (int kt = 0; kt < NLK / 64; kt++) {
        const int k0 = kt * 64;
        __syncthreads();   // previous iteration's reads of KPs/Vs complete

        // Load K tile transposed (Ks[d][k]) and V tile direct (Vs[k][d])
        #pragma unroll
        for (int u = 0; u < 4; u++) {
            int c = cb + u * 4;
            float4 kv = *(const float4*)&KW[(size_t)(k0 + lr) * ODIM + c];
            KPs[(c + 0) * 64 + lr] = kv.x;
            KPs[(c + 1) * 64 + lr] = kv.y;
            KPs[(c + 2) * 64 + lr] = kv.z;
            KPs[(c + 3) * 64 + lr] = kv.w;
            float4 vv = *(const float4*)&VW[(size_t)(k0 + lr) * ODIM + c];
            *(float4*)&Vs[lr * 64 + c] = vv;
        }
        __syncthreads();

        // S = Q @ K^T for this tile (4x4 fragment per thread)
        float s[4][4] = {};
        #pragma unroll 8
        for (int d = 0; d < 64; d++) {
            float4 av = *(const float4*)&Qs[d * 64 + ty * 4];
            float4 bv = *(const float4*)&KPs[d * 64 + tx * 4];
            float a[4] = {av.x, av.y, av.z, av.w};
            float bb[4] = {bv.x, bv.y, bv.z, bv.w};
            #pragma unroll
            for (int i = 0; i < 4; i++)
                #pragma unroll
                for (int j = 0; j < 4; j++)
                    s[i][j] = fmaf(a[i], bb[j], s[i][j]);
        }

        // scale + masks (fp32 arithmetic identical in structure to reference)
        float vmv[4];
        #pragma unroll
        for (int j = 0; j < 4; j++) vmv[j] = vm[k0 + tx * 4 + j];
        #pragma unroll
        for (int i = 0; i < 4; i++) {
            const int qg = q0 + ty * 4 + i;
            #pragma unroll
            for (int j = 0; j < 4; j++) {
                const int kg = k0 + tx * 4 + j;
                float x = s[i][j] * 0.125f;           // 1/sqrt(64)
                x -= (1.0f - vmv[j]) * BIGF;          // key padding
                if (kg <= qg) x -= BIGF;              // tril incl. diagonal
                s[i][j] = x;
            }
        }

        // Online softmax update (row stats shared across the 16 tx lanes)
        #pragma unroll
        for (int i = 0; i < 4; i++) {
            float rm = fmaxf(fmaxf(s[i][0], s[i][1]), fmaxf(s[i][2], s[i][3]));
            rm = fmaxf(rm, __shfl_xor_sync(0xffffffffu, rm, 1));
            rm = fmaxf(rm, __shfl_xor_sync(0xffffffffu, rm, 2));
            rm = fmaxf(rm, __shfl_xor_sync(0xffffffffu, rm, 4));
            rm = fmaxf(rm, __shfl_xor_sync(0xffffffffu, rm, 8));
            const float mnew = fmaxf(mrow[i], rm);
            const float sc = __expf(mrow[i] - mnew);   // exp(-inf)=0 first pass
            mrow[i] = mnew;
            float rs = 0.f;
            #pragma unroll
            for (int j = 0; j < 4; j++) {
                s[i][j] = __expf(s[i][j] - mnew);
                rs += s[i][j];
            }
            rs += __shfl_xor_sync(0xffffffffu, rs, 1);
            rs += __shfl_xor_sync(0xffffffffu, rs, 2);
            rs += __shfl_xor_sync(0xffffffffu, rs, 4);
            rs += __shfl_xor_sync(0xffffffffu, rs, 8);
            lrow[i] = lrow[i] * sc + rs;
            #pragma unroll
            for (int j = 0; j < 4; j++) o[i][j] *= sc;
        }

        __syncthreads();   // all Ks reads done before P overwrites the buffer

        // Write P into KPs as [k][q]
        #pragma unroll
        for (int i = 0; i < 4; i++)
            #pragma unroll
            for (int j = 0; j < 4; j++)
                KPs[(tx * 4 + j) * 64 + (ty * 4 + i)] = s[i][j];
        __syncthreads();

        // O += P @ V
        #pragma unroll 8
        for (int kk = 0; kk < 64; kk++) {
            float4 av = *(const float4*)&KPs[kk * 64 + ty * 4];
            float4 bv = *(const float4*)&Vs[kk * 64 + tx * 4];
            float a[4] = {av.x, av.y, av.z, av.w};
            float bb[4] = {bv.x, bv.y, bv.z, bv.w};
            #pragma unroll
            for (int i = 0; i < 4; i++)
                #pragma unroll
                for (int j = 0; j < 4; j++)
                    o[i][j] = fmaf(a[i], bb[j], o[i][j]);
        }
    }

    // Epilogue: normalize, apply q_mask, store
    #pragma unroll
    for (int i = 0; i < 4; i++) {
        const int qg = q0 + ty * 4 + i;
        const float qm = q_mask[(size_t)b * NLQ + qg];
        const float inv = qm / lrow[i];
        float4 r = make_float4(o[i][0] * inv, o[i][1] * inv,
                               o[i][2] * inv, o[i][3] * inv);
        *(float4*)&out[((size_t)b * NLQ + qg) * ODIM + h * DH + tx * 4] = r;
    }
}

// ---------------------------------------------------------------------------
extern "C" void kernel_launch(void* const* d_in, const int* in_sizes, int n_in,
                              void* d_out, int out_size)
{
    const float* q     = (const float*)d_in[0];
    const float* k     = (const float*)d_in[1];
    const float* v     = (const float*)d_in[2];
    const float* vmask = (const float*)d_in[3];
    const float* qmask = (const float*)d_in[4];
    const float* Wq    = (const float*)d_in[5];
    const float* Wk    = (const float*)d_in[6];
    const float* Wv    = (const float*)d_in[7];
    float* out = (float*)d_out;

    float *qw, *kw, *vw;
    cudaGetSymbolAddress((void**)&qw, g_QW);
    cudaGetSymbolAddress((void**)&kw, g_KW);
    cudaGetSymbolAddress((void**)&vw, g_VW);

    dim3 pg(ODIM / 64, (NB * NLQ) / 64);
    proj_gemm_kernel<<<pg, 256>>>(q, Wq, qw);
    proj_gemm_kernel<<<pg, 256>>>(k, Wk, kw);
    proj_gemm_kernel<<<pg, 256>>>(v, Wv, vw);

    attn_kernel<<<dim3(NLQ / 64, NHEADS, NB), 256>>>(vmask, qmask, out);
}

// round 5
// speedup vs baseline: 2.8196x; 2.8196x over previous
#include <cuda_runtime.h>
#include <cuda_bf16.h>
#include <cstdint>

#define ODIM 1024
#define XSZ  4194304        // 4096 tokens * 1024
#define WSZ  1048576
#define KOFF XSZ
#define VOFF (2*XSZ)
#define PITCH 144           // smem row pitch bytes (64 bf16 data + 16B pad)
#define NEG_INF __int_as_float(0xff800000)

__device__ __align__(16) __nv_bfloat16 g_xh[3*XSZ], g_xl[3*XSZ];
__device__ __align__(16) __nv_bfloat16 g_wh[3*WSZ], g_wl[3*WSZ];
__device__ __align__(16) __nv_bfloat16 g_ph[3*XSZ], g_pl[3*XSZ];

// ---------------- helpers ----------------
__device__ __forceinline__ uint32_t smem_u32(const void* p) {
    uint32_t a;
    asm("{ .reg .u64 t; cvta.to.shared.u64 t, %1; cvt.u32.u64 %0, t; }" : "=r"(a) : "l"(p));
    return a;
}
__device__ __forceinline__ uint32_t packbf2(float e0, float e1) {  // e0 -> low half
    uint32_t r;
    asm("cvt.rn.bf16x2.f32 %0, %2, %1;" : "=r"(r) : "f"(e0), "f"(e1));
    return r;
}
__device__ __forceinline__ float bfhi(float x) { return __bfloat162float(__float2bfloat16(x)); }
__device__ __forceinline__ void ldsm4(uint32_t* r, uint32_t a) {
    asm volatile("ldmatrix.sync.aligned.m8n8.x4.shared.b16 {%0,%1,%2,%3}, [%4];"
                 : "=r"(r[0]), "=r"(r[1]), "=r"(r[2]), "=r"(r[3]) : "r"(a));
}
__device__ __forceinline__ void ldsm4t(uint32_t* r, uint32_t a) {
    asm volatile("ldmatrix.sync.aligned.m8n8.x4.trans.shared.b16 {%0,%1,%2,%3}, [%4];"
                 : "=r"(r[0]), "=r"(r[1]), "=r"(r[2]), "=r"(r[3]) : "r"(a));
}
__device__ __forceinline__ void mma_bf16(float* d, const uint32_t* a, uint32_t b0, uint32_t b1) {
    asm volatile("mma.sync.aligned.m16n8k16.row.col.f32.bf16.bf16.f32 "
                 "{%0,%1,%2,%3}, {%4,%5,%6,%7}, {%8,%9}, {%0,%1,%2,%3};"
                 : "+f"(d[0]), "+f"(d[1]), "+f"(d[2]), "+f"(d[3])
                 : "r"(a[0]), "r"(a[1]), "r"(a[2]), "r"(a[3]), "r"(b0), "r"(b1));
}

// ---------------- split fp32 -> bf16 hi/lo ----------------
__global__ void split_kn(const float* __restrict__ s, __nv_bfloat16* __restrict__ h,
                         __nv_bfloat16* __restrict__ l, int n4) {
    int i = blockIdx.x * blockDim.x + threadIdx.x;
    if (i >= n4) return;
    float4 v = ((const float4*)s)[i];
    uint2 hh, ll;
    hh.x = packbf2(v.x, v.y);
    hh.y = packbf2(v.z, v.w);
    ll.x = packbf2(v.x - bfhi(v.x), v.y - bfhi(v.y));
    ll.y = packbf2(v.z - bfhi(v.z), v.w - bfhi(v.w));
    ((uint2*)h)[i] = hh;
    ((uint2*)l)[i] = ll;
}

// ---------------- projection: C[4096,1024] = X @ W^T, tile 64x64, BK=64 ----------------
__global__ __launch_bounds__(128) void proj_mma(
    const __nv_bfloat16* __restrict__ Ah_, const __nv_bfloat16* __restrict__ Al_,
    const __nv_bfloat16* __restrict__ Bh_, const __nv_bfloat16* __restrict__ Bl_,
    __nv_bfloat16* __restrict__ Ch, __nv_bfloat16* __restrict__ Cl)
{
    __shared__ __align__(16) char sAh[64*PITCH], sAl[64*PITCH];
    __shared__ __align__(16) char sBh[64*PITCH], sBl[64*PITCH];
    const int tid = threadIdx.x, wr = tid >> 5, lane = tid & 31;
    const int n0 = blockIdx.x * 64, m0 = blockIdx.y * 64;
    const int g = lane >> 2, t = lane & 3;
    const uint32_t bAh = smem_u32(sAh), bAl = smem_u32(sAl);
    const uint32_t bBh = smem_u32(sBh), bBl = smem_u32(sBl);
    float acc[8][4] = {};

    const uint32_t aOff = ((wr * 16 + (lane & 15)) * PITCH + (lane >> 4) * 16);
    const uint32_t rB   = ((lane >> 4) & 1) * 8 + (lane & 7);
    const uint32_t cBo  = ((lane >> 3) & 1) * 16;

    for (int kt = 0; kt < 16; kt++) {
        if (kt) __syncthreads();
        #pragma unroll
        for (int i = 0; i < 4; i++) {
            int idx = tid + 128 * i;          // 512 tasks = 64 rows x 8 chunks
            int r = (idx >> 3) & 63, gc = idx & 7;
            size_t goA = (size_t)(m0 + r) * ODIM + kt * 64 + gc * 8;
            size_t goB = (size_t)(n0 + r) * ODIM + kt * 64 + gc * 8;
            int so = r * PITCH + gc * 16;
            *(uint4*)(sAh + so) = *(const uint4*)(Ah_ + goA);
            *(uint4*)(sAl + so) = *(const uint4*)(Al_ + goA);
            *(uint4*)(sBh + so) = *(const uint4*)(Bh_ + goB);
            *(uint4*)(sBl + so) = *(const uint4*)(Bl_ + goB);
        }
        __syncthreads();
        #pragma unroll
        for (int kc = 0; kc < 4; kc++) {
            uint32_t ah[4], al[4];
            ldsm4(ah, bAh + aOff + kc * 32);
            ldsm4(al, bAl + aOff + kc * 32);
            #pragma unroll
            for (int jp = 0; jp < 4; jp++) {
                uint32_t bh[4], bl[4];
                uint32_t bo = (jp * 16 + rB) * PITCH + cBo + kc * 32;
                ldsm4(bh, bBh + bo);
                ldsm4(bl, bBl + bo);
                mma_bf16(acc[2*jp],   ah, bh[0], bh[1]);
                mma_bf16(acc[2*jp+1], ah, bh[2], bh[3]);
                mma_bf16(acc[2*jp],   ah, bl[0], bl[1]);
                mma_bf16(acc[2*jp+1], ah, bl[2], bl[3]);
                mma_bf16(acc[2*jp],   al, bh[0], bh[1]);
                mma_bf16(acc[2*jp+1], al, bh[2], bh[3]);
            }
        }
    }
    const int r0 = m0 + wr * 16 + g, r1 = r0 + 8;
    #pragma unroll
    for (int j = 0; j < 8; j++) {
        int col = n0 + j * 8 + 2 * t;
        float c0 = acc[j][0], c1 = acc[j][1], c2 = acc[j][2], c3 = acc[j][3];
        *(uint32_t*)(Ch + (size_t)r0 * ODIM + col) = packbf2(c0, c1);
        *(uint32_t*)(Ch + (size_t)r1 * ODIM + col) = packbf2(c2, c3);
        *(uint32_t*)(Cl + (size_t)r0 * ODIM + col) = packbf2(c0 - bfhi(c0), c1 - bfhi(c1));
        *(uint32_t*)(Cl + (size_t)r1 * ODIM + col) = packbf2(c2 - bfhi(c2), c3 - bfhi(c3));
    }
}

// ---------------- attention: 128 q-rows/CTA, 64-key tiles, causal skip ----------------
__global__ __launch_bounds__(256) void attn_mma(
    const float* __restrict__ v_mask, const float* __restrict__ q_mask,
    float* __restrict__ out,
    const __nv_bfloat16* __restrict__ Ph, const __nv_bfloat16* __restrict__ Pl)
{
    __shared__ __align__(16) char sKh[64*PITCH], sKl[64*PITCH];
    __shared__ __align__(16) char sVh[64*PITCH], sVl[64*PITCH];
    __shared__ float pen[64];
    const int tid = threadIdx.x, wr = tid >> 5, lane = tid & 31;
    const int qt = blockIdx.x, h = blockIdx.y, b = blockIdx.z;
    const int q0 = qt * 128;
    const int g = lane >> 2, t = lane & 3;
    const uint32_t bKh = smem_u32(sKh), bKl = smem_u32(sKl);
    const uint32_t bVh = smem_u32(sVh), bVl = smem_u32(sVl);

    const __nv_bfloat16* Qh_b = Ph + (size_t)(b * 2048 + q0) * ODIM + h * 64;
    const __nv_bfloat16* Ql_b = Pl + (size_t)(b * 2048 + q0) * ODIM + h * 64;
    const __nv_bfloat16* Kh_b = Ph + KOFF + (size_t)(b * 2048) * ODIM + h * 64;
    const __nv_bfloat16* Kl_b = Pl + KOFF + (size_t)(b * 2048) * ODIM + h * 64;
    const __nv_bfloat16* Vh_b = Ph + VOFF + (size_t)(b * 2048) * ODIM + h * 64;
    const __nv_bfloat16* Vl_b = Pl + VOFF + (size_t)(b * 2048) * ODIM + h * 64;
    const float* vm = v_mask + (size_t)b * 2048;

    // ---- stage Q through sKh/sKl in two 64-row passes, grab register fragments ----
    uint32_t qAh[4][4], qAl[4][4];
    #pragma unroll
    for (int p = 0; p < 2; p++) {
        if (p) __syncthreads();
        #pragma unroll
        for (int i = 0; i < 2; i++) {
            int idx = tid + 256 * i;          // 512 tasks = 64 rows x 8 chunks
            int r = (idx >> 3) & 63, gc = idx & 7;
            size_t go = (size_t)(p * 64 + r) * ODIM + gc * 8;
            int so = r * PITCH + gc * 16;
            *(uint4*)(sKh + so) = *(const uint4*)(Qh_b + go);
            *(uint4*)(sKl + so) = *(const uint4*)(Ql_b + go);
        }
        __syncthreads();
        if ((wr >> 2) == p) {
            const uint32_t aOff = ((wr & 3) * 16 + (lane & 15)) * PITCH + (lane >> 4) * 16;
            #pragma unroll
            for (int kc = 0; kc < 4; kc++) {
                ldsm4(qAh[kc], bKh + aOff + kc * 32);
                ldsm4(qAl[kc], bKl + aOff + kc * 32);
            }
        }
    }

    float oacc[8][4] = {};
    float lr0 = 0.f, lr1 = 0.f;
    const int qrow0 = q0 + wr * 16 + g;
    const uint32_t rB  = ((lane >> 4) & 1) * 8 + (lane & 7);
    const uint32_t cBo = ((lane >> 3) & 1) * 16;

    for (int kt2 = 2 * qt; kt2 < 32; kt2++) {
        const int k0 = kt2 * 64;
        __syncthreads();   // prior consumers of sK/sV (incl. Q staging) done
        #pragma unroll
        for (int i = 0; i < 2; i++) {
            int idx = tid + 256 * i;
            int r = (idx >> 3) & 63, gc = idx & 7;
            size_t go = (size_t)(k0 + r) * ODIM + gc * 8;
            int so = r * PITCH + gc * 16;
            *(uint4*)(sKh + so) = *(const uint4*)(Kh_b + go);
            *(uint4*)(sKl + so) = *(const uint4*)(Kl_b + go);
            *(uint4*)(sVh + so) = *(const uint4*)(Vh_b + go);
            *(uint4*)(sVl + so) = *(const uint4*)(Vl_b + go);
        }
        if (tid < 64) pen[tid] = (vm[k0 + tid] != 0.f) ? 0.f : NEG_INF;
        __syncthreads();

        #pragma unroll
        for (int jp = 0; jp < 4; jp++) {
            // ---- S: rows (qrow0, qrow0+8) x keys k0+jp*16..+15 ----
            float s8[8] = {};
            #pragma unroll
            for (int kc = 0; kc < 4; kc++) {
                uint32_t bh[4], bl[4];
                uint32_t bo = (jp * 16 + rB) * PITCH + cBo + kc * 32;
                ldsm4(bh, bKh + bo);
                ldsm4(bl, bKl + bo);
                mma_bf16(s8 + 0, qAh[kc], bh[0], bh[1]);
                mma_bf16(s8 + 4, qAh[kc], bh[2], bh[3]);
                mma_bf16(s8 + 0, qAh[kc], bl[0], bl[1]);
                mma_bf16(s8 + 4, qAh[kc], bl[2], bl[3]);
                mma_bf16(s8 + 0, qAl[kc], bh[0], bh[1]);
                mma_bf16(s8 + 4, qAl[kc], bh[2], bh[3]);
            }
            // ---- masks + exp (exact-zero semantics for masked/causal) ----
            float p[8];
            const int cb = jp * 16 + 2 * t;
            #pragma unroll
            for (int e = 0; e < 8; e++) {
                int tile = e >> 2, c = e & 3;
                int colL = cb + tile * 8 + (c & 1);
                int kg = k0 + colL;
                int qr = (c >= 2) ? qrow0 + 8 : qrow0;
                float x = s8[e] * 0.125f + pen[colL];
                p[e] = (kg <= qr) ? 0.f : __expf(x);
            }
            lr0 += p[0] + p[1] + p[4] + p[5];
            lr1 += p[2] + p[3] + p[6] + p[7];
            uint32_t pah[4], pal[4];
            pah[0] = packbf2(p[0], p[1]);  pah[1] = packbf2(p[2], p[3]);
            pah[2] = packbf2(p[4], p[5]);  pah[3] = packbf2(p[6], p[7]);
            pal[0] = packbf2(p[0] - bfhi(p[0]), p[1] - bfhi(p[1]));
            pal[1] = packbf2(p[2] - bfhi(p[2]), p[3] - bfhi(p[3]));
            pal[2] = packbf2(p[4] - bfhi(p[4]), p[5] - bfhi(p[5]));
            pal[3] = packbf2(p[6] - bfhi(p[6]), p[7] - bfhi(p[7]));
            // ---- O += P @ V ----
            #pragma unroll
            for (int j2 = 0; j2 < 4; j2++) {
                uint32_t vh[4], vl[4];
                uint32_t vo = (jp * 16 + (lane & 15)) * PITCH + (j2 * 2 + (lane >> 4)) * 16;
                ldsm4t(vh, bVh + vo);
                ldsm4t(vl, bVl + vo);
                mma_bf16(oacc[2*j2],   pah, vh[0], vh[1]);
                mma_bf16(oacc[2*j2+1], pah, vh[2], vh[3]);
                mma_bf16(oacc[2*j2],   pah, vl[0], vl[1]);
                mma_bf16(oacc[2*j2+1], pah, vl[2], vl[3]);
                mma_bf16(oacc[2*j2],   pal, vh[0], vh[1]);
                mma_bf16(oacc[2*j2+1], pal, vh[2], vh[3]);
            }
        }
    }

    // ---- epilogue ----
    lr0 += __shfl_xor_sync(0xffffffffu, lr0, 1);
    lr0 += __shfl_xor_sync(0xffffffffu, lr0, 2);
    lr1 += __shfl_xor_sync(0xffffffffu, lr1, 1);
    lr1 += __shfl_xor_sync(0xffffffffu, lr1, 2);
    const float qm0 = q_mask[(size_t)b * 2048 + qrow0];
    const float qm1 = q_mask[(size_t)b * 2048 + qrow0 + 8];
    const float inv0 = (lr0 > 0.f) ? qm0 / lr0 : 0.f;
    const float inv1 = (lr1 > 0.f) ? qm1 / lr1 : 0.f;
    float* o0 = out + (size_t)(b * 2048 + qrow0) * ODIM + h * 64;
    float* o1 = o0 + (size_t)8 * ODIM;
    #pragma unroll
    for (int j = 0; j < 8; j++) {
        *(float2*)(o0 + j * 8 + 2 * t) = make_float2(oacc[j][0] * inv0, oacc[j][1] * inv0);
        *(float2*)(o1 + j * 8 + 2 * t) = make_float2(oacc[j][2] * inv1, oacc[j][3] * inv1);
    }
}

// ---------------- degenerate rows (q >= last valid key): exact tie-average ----------------
__global__ void fallback_k(const float* __restrict__ v_mask, const float* __restrict__ q_mask,
                           float* __restrict__ out,
                           const __nv_bfloat16* __restrict__ Vh, const __nv_bfloat16* __restrict__ Vl)
{
    const int h = blockIdx.x, b = blockIdx.y, d = threadIdx.x;  // 64 threads
    __shared__ int s_kmax, s_cnt;
    const float* vm = v_mask + (size_t)b * 2048;
    if (d == 0) {
        int km = 0, c = 0;
        for (int k2 = 0; k2 < 2048; k2++) if (vm[k2] != 0.f) { km = k2; c++; }
        s_kmax = km; s_cnt = c;
    }
    const __nv_bfloat16* vh = Vh + (size_t)(b * 2048) * ODIM + h * 64 + d;
    const __nv_bfloat16* vl = Vl + (size_t)(b * 2048) * ODIM + h * 64 + d;
    float tm = 0.f;
    for (int k2 = 0; k2 < 2048; k2++)
        if (vm[k2] != 0.f)
            tm += __bfloat162float(vh[(size_t)k2 * ODIM]) + __bfloat162float(vl[(size_t)k2 * ODIM]);
    __syncthreads();
    const int kmax = s_kmax, cnt = s_cnt;
    float suf = 0.f;
    for (int k2 = 2047; k2 >= kmax; k2--) {
        const float qm = q_mask[(size_t)b * 2048 + k2];
        const int den = cnt + (2047 - k2);
        out[((size_t)(b * 2048 + k2)) * ODIM + h * 64 + d] =
            (den > 0) ? qm * (tm + suf) / (float)den : 0.f;
        suf += __bfloat162float(vh[(size_t)k2 * ODIM]) + __bfloat162float(vl[(size_t)k2 * ODIM]);
    }
}

// ---------------- launch ----------------
extern "C" void kernel_launch(void* const* d_in, const int* in_sizes, int n_in,
                              void* d_out, int out_size)
{
    const float* q     = (const float*)d_in[0];
    const float* k     = (const float*)d_in[1];
    const float* v     = (const float*)d_in[2];
    const float* vmask = (const float*)d_in[3];
    const float* qmask = (const float*)d_in[4];
    const float* Wq    = (const float*)d_in[5];
    const float* Wk    = (const float*)d_in[6];
    const float* Wv    = (const float*)d_in[7];
    float* out = (float*)d_out;

    __nv_bfloat16 *xh, *xl, *wh, *wl, *ph, *pl;
    cudaGetSymbolAddress((void**)&xh, g_xh);
    cudaGetSymbolAddress((void**)&xl, g_xl);
    cudaGetSymbolAddress((void**)&wh, g_wh);
    cudaGetSymbolAddress((void**)&wl, g_wl);
    cudaGetSymbolAddress((void**)&ph, g_ph);
    cudaGetSymbolAddress((void**)&pl, g_pl);

    split_kn<<<4096, 256>>>(q, xh,          xl,          XSZ / 4);
    split_kn<<<4096, 256>>>(k, xh + XSZ,    xl + XSZ,    XSZ / 4);
    split_kn<<<4096, 256>>>(v, xh + 2*XSZ,  xl + 2*XSZ,  XSZ / 4);
    split_kn<<<1024, 256>>>(Wq, wh,         wl,          WSZ / 4);
    split_kn<<<1024, 256>>>(Wk, wh + WSZ,   wl + WSZ,    WSZ / 4);
    split_kn<<<1024, 256>>>(Wv, wh + 2*WSZ, wl + 2*WSZ,  WSZ / 4);

    for (int s = 0; s < 3; s++)
        proj_mma<<<dim3(16, 64), 128>>>(
            xh + s * XSZ, xl + s * XSZ, wh + s * WSZ, wl + s * WSZ,
            ph + s * XSZ, pl + s * XSZ);

    attn_mma<<<dim3(16, 16, 2), 256>>>(vmask, qmask, out, ph, pl);
    fallback_k<<<dim3(16, 2), 64>>>(vmask, qmask, out, ph + 2*XSZ, pl + 2*XSZ);
}